// round 13
// baseline (speedup 1.0000x reference)
#include <cuda_runtime.h>
#include <cuda_bf16.h>
#include <math.h>

#define Bb 16
#define Nn 1000
#define Hh 128
#define Mm 2
#define Tt 16
#define Ss 25         // chunks per (b,m): CN rows each
#define CN 40         // Nn / Ss; 8 warps x 5 rows
#define NEGC 1e8f
#define CCLIP 10.0f

// ---------------- scratch (static device globals; no allocation) ----------------
#define BNH (Bb*Nn*Hh)
__device__ __align__(16) __nv_bfloat16 d_r1[Mm*BNH];
__device__ __align__(16) __nv_bfloat16 d_v1[Mm*BNH];
__device__ __align__(16) __nv_bfloat16 d_r3[Mm*BNH];
__device__ __align__(16) __nv_bfloat16 d_v3[Mm*BNH];
__device__ __align__(16) __nv_bfloat16 d_r4[Mm*BNH];
__device__ __align__(16) __nv_bfloat16 d_v4[Mm*BNH];
__device__ __align__(16) float d_r2[BNH];          // pointer path stays fp32
__device__ __align__(16) float d_hmean[Bb*Hh];
__device__ __align__(16) float d_qproj[Bb*Mm*Hh];  // projected glimpse-1 query
__device__ __align__(16) float d_mask[Bb*Nn];
__device__ __align__(16) float d_u[Bb*Nn];         // pointer logits
// double-buffered glimpse partials: chunk(k) reads buf[rb], writes buf[wb]
__device__ __align__(16) float d_pZ[2][Bb*Mm*Ss];
__device__ __align__(16) float d_pacc[2][Bb*Mm*Ss*Hh];

__device__ __forceinline__ float fast_tanh(float x) {
    float y;
    asm("tanh.approx.f32 %0, %1;" : "=f"(y) : "f"(x));
    return y;
}

// ---------------- precompute GEMM: 13 slabs of [16000x128] @ [128x128] (SIMT) ------
struct GemmW {
    const float* Wref1; const float* Vec1;
    const float* Wref3; const float* Vec3;
    const float* Wref4; const float* Vec4;
    const float* Wref2;
};

__global__ __launch_bounds__(256) void gemm_kernel(const float* __restrict__ A, GemmW gw) {
    __shared__ float As[8][132];
    __shared__ float Bs[8][132];

    int s = blockIdx.y;
    int m = s & 1;
    const float* W;
    __nv_bfloat16* Db = nullptr;
    float* Df = nullptr;
    switch (s >> 1) {
        case 0: W = gw.Wref1; Db = d_r1; break;
        case 1: W = gw.Vec1;  Db = d_v1; break;
        case 2: W = gw.Wref3; Db = d_r3; break;
        case 3: W = gw.Vec3;  Db = d_v3; break;
        case 4: W = gw.Wref4; Db = d_r4; break;
        case 5: W = gw.Vec4;  Db = d_v4; break;
        default: W = gw.Wref2; Df = d_r2; break;   // s==12 -> m==0
    }
    W += (size_t)m * Hh * Hh;
    if (Db) Db += (size_t)m * BNH;

    int tid = threadIdx.x;
    int tx = tid & 15, ty = tid >> 4;
    int rowBase = blockIdx.x * 128;

    int arow = tid >> 1, akq = (tid & 1) * 4;
    int brow = tid >> 5, bcol = (tid & 31) * 4;

    float acc[8][8];
#pragma unroll
    for (int i = 0; i < 8; i++)
#pragma unroll
        for (int j = 0; j < 8; j++) acc[i][j] = 0.f;

    for (int k0 = 0; k0 < 128; k0 += 8) {
        float4 av = *(const float4*)&A[(size_t)(rowBase + arow) * 128 + k0 + akq];
        As[akq + 0][arow] = av.x;
        As[akq + 1][arow] = av.y;
        As[akq + 2][arow] = av.z;
        As[akq + 3][arow] = av.w;
        float4 bv = *(const float4*)&W[(size_t)(k0 + brow) * 128 + bcol];
        *(float4*)&Bs[brow][bcol] = bv;
        __syncthreads();
#pragma unroll
        for (int kk = 0; kk < 8; kk++) {
            float4 a0 = *(float4*)&As[kk][ty * 8];
            float4 a1 = *(float4*)&As[kk][ty * 8 + 4];
            float4 b0 = *(float4*)&Bs[kk][tx * 4];
            float4 b1 = *(float4*)&Bs[kk][64 + tx * 4];
            float a[8] = {a0.x, a0.y, a0.z, a0.w, a1.x, a1.y, a1.z, a1.w};
            float b[8] = {b0.x, b0.y, b0.z, b0.w, b1.x, b1.y, b1.z, b1.w};
#pragma unroll
            for (int i = 0; i < 8; i++)
#pragma unroll
                for (int j = 0; j < 8; j++) acc[i][j] = fmaf(a[i], b[j], acc[i][j]);
        }
        __syncthreads();
    }

    int r0 = rowBase + ty * 8;
    if (Db) {
#pragma unroll
        for (int i = 0; i < 8; i++) {
            __nv_bfloat162 p01 = __floats2bfloat162_rn(acc[i][0], acc[i][1]);
            __nv_bfloat162 p23 = __floats2bfloat162_rn(acc[i][2], acc[i][3]);
            __nv_bfloat162 p45 = __floats2bfloat162_rn(acc[i][4], acc[i][5]);
            __nv_bfloat162 p67 = __floats2bfloat162_rn(acc[i][6], acc[i][7]);
            uint2 lo, hi;
            lo.x = *(unsigned int*)&p01; lo.y = *(unsigned int*)&p23;
            hi.x = *(unsigned int*)&p45; hi.y = *(unsigned int*)&p67;
            *(uint2*)&Db[(size_t)(r0 + i) * Hh + tx * 4] = lo;
            *(uint2*)&Db[(size_t)(r0 + i) * Hh + 64 + tx * 4] = hi;
        }
    } else {
#pragma unroll
        for (int i = 0; i < 8; i++) {
            float4 o0 = make_float4(acc[i][0], acc[i][1], acc[i][2], acc[i][3]);
            float4 o1 = make_float4(acc[i][4], acc[i][5], acc[i][6], acc[i][7]);
            *(float4*)&Df[(size_t)(r0 + i) * Hh + tx * 4] = o0;
            *(float4*)&Df[(size_t)(r0 + i) * Hh + 64 + tx * 4] = o1;
        }
    }
}

// ---------------- h_mean ----------------
__global__ __launch_bounds__(256) void hmean_kernel(const float* __restrict__ enc) {
    int b = blockIdx.x;
    int h = threadIdx.x & 127;
    int part = threadIdx.x >> 7;
    float sum = 0.f;
    int n0 = part * 500;
    for (int n = n0; n < n0 + 500; n++) sum += enc[(size_t)(b * Nn + n) * Hh + h];
    __shared__ float sp[256];
    sp[threadIdx.x] = sum;
    __syncthreads();
    if (part == 0) d_hmean[b * Hh + h] = (sp[h] + sp[128 + h]) * (1.0f / (float)Nn);
}

// ---------------- init: mask copy + first-step Wq1 projection ----------------
__global__ __launch_bounds__(256) void init_kernel(const float* __restrict__ mask0,
                                                   const float* __restrict__ dec_inp,
                                                   const float* __restrict__ Wq1) {
    int b = blockIdx.x, tid = threadIdx.x;
    __shared__ float sq0[256];
    sq0[tid] = (tid < 128) ? d_hmean[b * Hh + tid] : dec_inp[tid - 128];
    for (int n = tid; n < Nn; n += 256) d_mask[b * Nn + n] = mask0[b * Nn + n];
    __syncthreads();
    int m = tid >> 7, h = tid & 127;
    const float* W = Wq1 + (size_t)m * 256 * Hh;
    float acc = 0.f;
#pragma unroll 8
    for (int i = 0; i < 256; i++) acc = fmaf(sq0[i], W[(size_t)i * Hh + h], acc);
    d_qproj[(b * Mm + m) * Hh + h] = acc;
}

// ---------------- glimpse chunk with fused combine PROLOGUE -------------------------
// grid (Ss, Mm, Bb), 256 threads = 8 warps x 5 rows.
// which==0: query from d_qproj (written by init/finalize); writes buf0.
// which==1: prologue = combine(glimpse0, buf0) + Wq(=Wq3) projection; writes buf1.
// which==2: prologue = combine(glimpse1, buf1) + Wq(=Wq4) projection; writes buf0.
// Prologue reads partials written by the PREVIOUS kernel (complete at launch);
// double buffering removes any read/write overlap within this kernel.
__global__ __launch_bounds__(256, 4) void glimpse_chunk(int which,
                                                        const float* __restrict__ Wmh,
                                                        const float* __restrict__ Wq) {
    const __nv_bfloat16* rT = (which == 0) ? d_r1 : (which == 1) ? d_r3 : d_r4;
    const __nv_bfloat16* vT = (which == 0) ? d_v1 : (which == 1) ? d_v3 : d_v4;
    int wb = (which == 1) ? 1 : 0;
    int rb = (which == 2) ? 1 : 0;

    int c = blockIdx.x, m = blockIdx.y, b = blockIdx.z;
    int tid = threadIdx.x, lane = tid & 31, w = tid >> 5;

    __shared__ float wZ[8];
    __shared__ __align__(16) float wacc[8 * 128];
    __shared__ float sg[256];
    __shared__ __align__(16) float sq[128];

    float4 q4;
    if (which == 0) {
        q4 = *(const float4*)&d_qproj[((size_t)(b * Mm + m)) * Hh + lane * 4];
    } else {
        // ---- fused combine prologue ----
        int mm = tid >> 7, h = tid & 127;
        const float* pZr = d_pZ[rb];
        const float* paccr = d_pacc[rb];
        int base = (b * Mm + mm) * Ss;
        float z = 0.f, g = 0.f;
#pragma unroll
        for (int cc = 0; cc < Ss; cc++) {
            z += pZr[base + cc];
            g += paccr[(base + cc) * Hh + h];
        }
        sg[tid] = g / z;
        __syncthreads();
        // qb[h] = sum_j sg[j]*Wmh[j,h], split j over 2 halves (reuse wacc as scratch)
        {
            int j0 = mm * 128;
            float o = 0.f;
#pragma unroll 8
            for (int j = j0; j < j0 + 128; j++) o = fmaf(sg[j], Wmh[(size_t)j * Hh + h], o);
            wacc[tid] = o;
            __syncthreads();
            if (mm == 0) sq[h] = wacc[h] + wacc[128 + h];   // sq = qb temporarily
            __syncthreads();
        }
        // q[h] = sum_i qb[i] * Wq[m,i,h], split i over 2 halves
        {
            const float* Wqm = Wq + (size_t)m * Hh * Hh;
            int i0 = mm * 64;
            float acc = 0.f;
#pragma unroll 8
            for (int i = i0; i < i0 + 64; i++) acc = fmaf(sq[i], Wqm[(size_t)i * Hh + h], acc);
            wacc[tid] = acc;
            __syncthreads();
            float qv = (mm == 0) ? (wacc[h] + wacc[128 + h]) : 0.f;
            __syncthreads();
            if (mm == 0) sg[h] = qv;                        // sg[0..127] = q
            __syncthreads();
        }
        q4 = *(float4*)&sg[lane * 4];
        __syncthreads();
    }

    const __nv_bfloat16* rBase = rT + (size_t)(m * Bb + b) * Nn * Hh;
    const __nv_bfloat16* vBase = vT + (size_t)(m * Bb + b) * Nn * Hh;
    const float* maskb = d_mask + b * Nn;

    int n0 = c * CN + w;

    // front-batched loads: 11 independent LDGs in flight (8B each for r/v)
    uint2 rw[5], vw[5];
    float mk[5];
#pragma unroll
    for (int i = 0; i < 5; i++) {
        int n = n0 + i * 8;
        rw[i] = *(const uint2*)&rBase[(size_t)n * Hh + lane * 4];
        vw[i] = *(const uint2*)&vBase[(size_t)n * Hh + lane * 4];
        mk[i] = maskb[n];
    }

    float rf[5][4], vf[5][4];
#pragma unroll
    for (int i = 0; i < 5; i++) {
        float2 r01 = __bfloat1622float2(*(__nv_bfloat162*)&rw[i].x);
        float2 r23 = __bfloat1622float2(*(__nv_bfloat162*)&rw[i].y);
        float2 v01 = __bfloat1622float2(*(__nv_bfloat162*)&vw[i].x);
        float2 v23 = __bfloat1622float2(*(__nv_bfloat162*)&vw[i].y);
        rf[i][0] = r01.x; rf[i][1] = r01.y; rf[i][2] = r23.x; rf[i][3] = r23.y;
        vf[i][0] = v01.x; vf[i][1] = v01.y; vf[i][2] = v23.x; vf[i][3] = v23.y;
    }

    float dot[5];
#pragma unroll
    for (int i = 0; i < 5; i++) {
        float d = fast_tanh(q4.x + rf[i][0]) * vf[i][0];
        d = fmaf(fast_tanh(q4.y + rf[i][1]), vf[i][1], d);
        d = fmaf(fast_tanh(q4.z + rf[i][2]), vf[i][2], d);
        d = fmaf(fast_tanh(q4.w + rf[i][3]), vf[i][3], d);
        dot[i] = d;
    }
#pragma unroll
    for (int off = 16; off; off >>= 1) {
#pragma unroll
        for (int i = 0; i < 5; i++) dot[i] += __shfl_xor_sync(0xffffffffu, dot[i], off);
    }

    float Z = 0.f;
    float4 racc = make_float4(0.f, 0.f, 0.f, 0.f);
#pragma unroll
    for (int i = 0; i < 5; i++) {
        float p = __expf(fmaf(CCLIP, fast_tanh(dot[i]), -CCLIP) - NEGC * mk[i]);
        Z += p;
        racc.x = fmaf(p, rf[i][0], racc.x);
        racc.y = fmaf(p, rf[i][1], racc.y);
        racc.z = fmaf(p, rf[i][2], racc.z);
        racc.w = fmaf(p, rf[i][3], racc.w);
    }

    if (lane == 0) wZ[w] = Z;
    *(float4*)&wacc[w * 128 + lane * 4] = racc;
    __syncthreads();

    if (tid < 128) {
        float z = 0.f, g = 0.f;
#pragma unroll
        for (int j = 0; j < 8; j++) {
            z += wZ[j];
            g += wacc[j * 128 + tid];
        }
        int pidx = (b * Mm + m) * Ss + c;
        d_pacc[wb][pidx * Hh + tid] = g;
        if (tid == 0) d_pZ[wb][pidx] = z;
    }
}

// ---------------- pointer logits with fused combine(glimpse2) prologue -------------
// grid (Ss, Bb), 256 threads. Prologue reads buf0 (written by chunk(2)).
__global__ __launch_bounds__(256, 3) void logits_chunk(const float* __restrict__ Vec2,
                                                       const float* __restrict__ Wmh,
                                                       const float* __restrict__ Wq2) {
    int c = blockIdx.x, b = blockIdx.y;
    int tid = threadIdx.x, lane = tid & 31, w = tid >> 5;

    __shared__ float sg[256];
    __shared__ float sp[256];
    __shared__ __align__(16) float sq[128];

    // ---- fused combine prologue (glimpse 2 partials, buf0) ----
    {
        int mm = tid >> 7, h = tid & 127;
        int base = (b * Mm + mm) * Ss;
        float z = 0.f, g = 0.f;
#pragma unroll
        for (int cc = 0; cc < Ss; cc++) {
            z += d_pZ[0][base + cc];
            g += d_pacc[0][(base + cc) * Hh + h];
        }
        sg[tid] = g / z;
        __syncthreads();
        {
            int j0 = mm * 128;
            float o = 0.f;
#pragma unroll 8
            for (int j = j0; j < j0 + 128; j++) o = fmaf(sg[j], Wmh[(size_t)j * Hh + h], o);
            sp[tid] = o;
            __syncthreads();
            if (mm == 0) sq[h] = sp[h] + sp[128 + h];       // qb
            __syncthreads();
        }
        {
            int i0 = mm * 64;
            float acc = 0.f;
#pragma unroll 8
            for (int i = i0; i < i0 + 64; i++) acc = fmaf(sq[i], Wq2[(size_t)i * Hh + h], acc);
            sp[tid] = acc;
            __syncthreads();
            float qv = (mm == 0) ? (sp[h] + sp[128 + h]) : 0.f;
            __syncthreads();
            if (mm == 0) sg[h] = qv;                        // sg[0..127] = q2
            __syncthreads();
        }
    }
    float4 q4 = *(float4*)&sg[lane * 4];
    float4 v2 = *(const float4*)&Vec2[lane * 4];
    const float* rBase = d_r2 + (size_t)b * Nn * Hh;
    const float* maskb = d_mask + b * Nn;

    int n0 = c * CN + w;
    float4 r[5];
    float mk[5];
#pragma unroll
    for (int i = 0; i < 5; i++) {
        int n = n0 + i * 8;
        r[i] = *(const float4*)&rBase[(size_t)n * Hh + lane * 4];
        mk[i] = maskb[n];
    }
    float dot[5];
#pragma unroll
    for (int i = 0; i < 5; i++) {
        float d = fast_tanh(q4.x + r[i].x) * v2.x;
        d = fmaf(fast_tanh(q4.y + r[i].y), v2.y, d);
        d = fmaf(fast_tanh(q4.z + r[i].z), v2.z, d);
        d = fmaf(fast_tanh(q4.w + r[i].w), v2.w, d);
        dot[i] = d;
    }
#pragma unroll
    for (int off = 16; off; off >>= 1) {
#pragma unroll
        for (int i = 0; i < 5; i++) dot[i] += __shfl_xor_sync(0xffffffffu, dot[i], off);
    }
    if (lane == 0) {
#pragma unroll
        for (int i = 0; i < 5; i++)
            d_u[b * Nn + n0 + i * 8] = CCLIP * fast_tanh(dot[i]) - NEGC * mk[i];
    }
}

// ---------------- finalize: log_softmax, argmax, output, state, next projection ----
__global__ __launch_bounds__(1024) void pointer_finalize(const float* __restrict__ enc,
                                                         const float* __restrict__ Wq1,
                                                         float* __restrict__ out, int t) {
    int b = blockIdx.x, tid = threadIdx.x;
    __shared__ float rv[1024];
    __shared__ int ri[1024];
    __shared__ float sred[1024];
    __shared__ float sq0[256];

    float u = (tid < Nn) ? d_u[b * Nn + tid] : -1e30f;

    // argmax (first index wins on ties, matching jnp.argmax)
    rv[tid] = u; ri[tid] = (tid < Nn) ? tid : 0;
    __syncthreads();
#pragma unroll
    for (int s = 512; s; s >>= 1) {
        if (tid < s) {
            float v2 = rv[tid + s]; int i2 = ri[tid + s];
            if (v2 > rv[tid] || (v2 == rv[tid] && i2 < ri[tid])) { rv[tid] = v2; ri[tid] = i2; }
        }
        __syncthreads();
    }
    int sel = ri[0];

    // fixed-shift lse: u <= 10 always
    sred[tid] = (tid < Nn) ? __expf(u - CCLIP) : 0.f;
    __syncthreads();
#pragma unroll
    for (int s = 512; s; s >>= 1) {
        if (tid < s) sred[tid] += sred[tid + s];
        __syncthreads();
    }
    float lse = CCLIP + __logf(sred[0]);

    if (tid < Nn)
        out[((size_t)t * Bb + b) * Nn + tid] = u - lse;
    if (tid == 0) {
        out[(size_t)Tt * Bb * Nn + t * Bb + b] = (float)sel;
        d_mask[b * Nn + sel] = 1.0f;
    }

    // q0 = [h_mean, enc[b, sel]]; project with Wq1 for next step's glimpse 1
    if (tid < 256)
        sq0[tid] = (tid < 128) ? d_hmean[b * Hh + tid]
                               : enc[((size_t)b * Nn + sel) * Hh + (tid - 128)];
    __syncthreads();
    {
        int part = tid >> 8;          // 4 parts
        int mh = tid & 255;
        int m = mh >> 7, h = mh & 127;
        const float* W = Wq1 + (size_t)m * 256 * Hh;
        int i0 = part * 64;
        float acc = 0.f;
#pragma unroll 8
        for (int i = i0; i < i0 + 64; i++) acc = fmaf(sq0[i], W[(size_t)i * Hh + h], acc);
        sred[tid] = acc;
        __syncthreads();
        if (tid < 256) {
            float a = sred[tid] + sred[tid + 256] + sred[tid + 512] + sred[tid + 768];
            d_qproj[(b * Mm + m) * Hh + h] = a;
        }
    }
}

// ---------------- host launcher ----------------
extern "C" void kernel_launch(void* const* d_in, const int* in_sizes, int n_in,
                              void* d_out, int out_size) {
    const float* enc    = (const float*)d_in[0];
    const float* mask0  = (const float*)d_in[1];
    const float* Wq1    = (const float*)d_in[2];
    const float* Wref1  = (const float*)d_in[3];
    const float* Vec1   = (const float*)d_in[4];
    const float* Wq3    = (const float*)d_in[5];
    const float* Wref3  = (const float*)d_in[6];
    const float* Vec3   = (const float*)d_in[7];
    const float* Wq4    = (const float*)d_in[8];
    const float* Wref4  = (const float*)d_in[9];
    const float* Vec4   = (const float*)d_in[10];
    const float* Wmh    = (const float*)d_in[11];
    const float* Wq2    = (const float*)d_in[12];
    const float* Wref2  = (const float*)d_in[13];
    const float* Vec2   = (const float*)d_in[14];
    const float* dec_inp = (const float*)d_in[15];
    float* out = (float*)d_out;

    GemmW gw{Wref1, Vec1, Wref3, Vec3, Wref4, Vec4, Wref2};
    gemm_kernel<<<dim3(125, 13), 256>>>(enc, gw);
    hmean_kernel<<<Bb, 256>>>(enc);
    init_kernel<<<Bb, 256>>>(mask0, dec_inp, Wq1);

    for (int t = 0; t < Tt; t++) {
        glimpse_chunk<<<dim3(Ss, Mm, Bb), 256>>>(0, Wmh, Wq3);
        glimpse_chunk<<<dim3(Ss, Mm, Bb), 256>>>(1, Wmh, Wq3);
        glimpse_chunk<<<dim3(Ss, Mm, Bb), 256>>>(2, Wmh, Wq4);
        logits_chunk<<<dim3(Ss, Bb), 256>>>(Vec2, Wmh, Wq2);
        pointer_finalize<<<Bb, 1024>>>(enc, Wq1, out, t);
    }
    (void)in_sizes; (void)n_in; (void)out_size;
}

// round 14
// speedup vs baseline: 1.1176x; 1.1176x over previous
#include <cuda_runtime.h>
#include <cuda_bf16.h>
#include <math.h>

#define Bb 16
#define Nn 1000
#define NP 1024       // padded scan length (rows >= Nn forced to weight 0)
#define Hh 128
#define Mm 2
#define Tt 16
#define Ss 16         // chunks per (b,m): CN rows each (over padded NP)
#define CN 64         // NP / Ss; 8 warps x 8 rows
#define SsL 16        // logits chunks
#define NEGC 1e8f
#define CCLIP 10.0f

// ---------------- scratch (static device globals; no allocation) ----------------
// r/v arrays padded by 4096 elements (32 rows) so reads at rows [1000,1024) of the
// LAST slab stay in-bounds; earlier slabs overrun into the next slab (valid, masked).
#define BNH (Bb*Nn*Hh)
#define PAD (32*Hh)
__device__ __align__(16) __nv_bfloat16 d_r1[Mm*BNH + PAD];
__device__ __align__(16) __nv_bfloat16 d_v1[Mm*BNH + PAD];
__device__ __align__(16) __nv_bfloat16 d_r3[Mm*BNH + PAD];
__device__ __align__(16) __nv_bfloat16 d_v3[Mm*BNH + PAD];
__device__ __align__(16) __nv_bfloat16 d_r4[Mm*BNH + PAD];
__device__ __align__(16) __nv_bfloat16 d_v4[Mm*BNH + PAD];
__device__ __align__(16) float d_r2[BNH + PAD];    // pointer path stays fp32
__device__ __align__(16) float d_hmean[Bb*Hh];
__device__ __align__(16) float d_qproj[Bb*Mm*Hh];  // projected glimpse query per head
__device__ __align__(16) float d_qp2[Bb*Hh];       // projected pointer query
__device__ __align__(16) float d_mask[Bb*Nn + 64];
__device__ __align__(16) float d_u[Bb*Nn];         // pointer logits
__device__ __align__(16) float d_pZ[Bb*Mm*Ss];
__device__ __align__(16) float d_pacc[Bb*Mm*Ss*Hh];

__device__ __forceinline__ float fast_tanh(float x) {
    float y;
    asm("tanh.approx.f32 %0, %1;" : "=f"(y) : "f"(x));
    return y;
}

// ---------------- precompute GEMM: 13 slabs of [16000x128] @ [128x128] (SIMT) ------
struct GemmW {
    const float* Wref1; const float* Vec1;
    const float* Wref3; const float* Vec3;
    const float* Wref4; const float* Vec4;
    const float* Wref2;
};

__global__ __launch_bounds__(256) void gemm_kernel(const float* __restrict__ A, GemmW gw) {
    __shared__ float As[8][132];
    __shared__ float Bs[8][132];

    int s = blockIdx.y;
    int m = s & 1;
    const float* W;
    __nv_bfloat16* Db = nullptr;
    float* Df = nullptr;
    switch (s >> 1) {
        case 0: W = gw.Wref1; Db = d_r1; break;
        case 1: W = gw.Vec1;  Db = d_v1; break;
        case 2: W = gw.Wref3; Db = d_r3; break;
        case 3: W = gw.Vec3;  Db = d_v3; break;
        case 4: W = gw.Wref4; Db = d_r4; break;
        case 5: W = gw.Vec4;  Db = d_v4; break;
        default: W = gw.Wref2; Df = d_r2; break;   // s==12 -> m==0
    }
    W += (size_t)m * Hh * Hh;
    if (Db) Db += (size_t)m * BNH;

    int tid = threadIdx.x;
    int tx = tid & 15, ty = tid >> 4;
    int rowBase = blockIdx.x * 128;

    int arow = tid >> 1, akq = (tid & 1) * 4;
    int brow = tid >> 5, bcol = (tid & 31) * 4;

    float acc[8][8];
#pragma unroll
    for (int i = 0; i < 8; i++)
#pragma unroll
        for (int j = 0; j < 8; j++) acc[i][j] = 0.f;

    for (int k0 = 0; k0 < 128; k0 += 8) {
        float4 av = *(const float4*)&A[(size_t)(rowBase + arow) * 128 + k0 + akq];
        As[akq + 0][arow] = av.x;
        As[akq + 1][arow] = av.y;
        As[akq + 2][arow] = av.z;
        As[akq + 3][arow] = av.w;
        float4 bv = *(const float4*)&W[(size_t)(k0 + brow) * 128 + bcol];
        *(float4*)&Bs[brow][bcol] = bv;
        __syncthreads();
#pragma unroll
        for (int kk = 0; kk < 8; kk++) {
            float4 a0 = *(float4*)&As[kk][ty * 8];
            float4 a1 = *(float4*)&As[kk][ty * 8 + 4];
            float4 b0 = *(float4*)&Bs[kk][tx * 4];
            float4 b1 = *(float4*)&Bs[kk][64 + tx * 4];
            float a[8] = {a0.x, a0.y, a0.z, a0.w, a1.x, a1.y, a1.z, a1.w};
            float b[8] = {b0.x, b0.y, b0.z, b0.w, b1.x, b1.y, b1.z, b1.w};
#pragma unroll
            for (int i = 0; i < 8; i++)
#pragma unroll
                for (int j = 0; j < 8; j++) acc[i][j] = fmaf(a[i], b[j], acc[i][j]);
        }
        __syncthreads();
    }

    int r0 = rowBase + ty * 8;
    if (Db) {
#pragma unroll
        for (int i = 0; i < 8; i++) {
            __nv_bfloat162 p01 = __floats2bfloat162_rn(acc[i][0], acc[i][1]);
            __nv_bfloat162 p23 = __floats2bfloat162_rn(acc[i][2], acc[i][3]);
            __nv_bfloat162 p45 = __floats2bfloat162_rn(acc[i][4], acc[i][5]);
            __nv_bfloat162 p67 = __floats2bfloat162_rn(acc[i][6], acc[i][7]);
            uint2 lo, hi;
            lo.x = *(unsigned int*)&p01; lo.y = *(unsigned int*)&p23;
            hi.x = *(unsigned int*)&p45; hi.y = *(unsigned int*)&p67;
            *(uint2*)&Db[(size_t)(r0 + i) * Hh + tx * 4] = lo;
            *(uint2*)&Db[(size_t)(r0 + i) * Hh + 64 + tx * 4] = hi;
        }
    } else {
#pragma unroll
        for (int i = 0; i < 8; i++) {
            float4 o0 = make_float4(acc[i][0], acc[i][1], acc[i][2], acc[i][3]);
            float4 o1 = make_float4(acc[i][4], acc[i][5], acc[i][6], acc[i][7]);
            *(float4*)&Df[(size_t)(r0 + i) * Hh + tx * 4] = o0;
            *(float4*)&Df[(size_t)(r0 + i) * Hh + 64 + tx * 4] = o1;
        }
    }
}

// ---------------- h_mean ----------------
__global__ __launch_bounds__(256) void hmean_kernel(const float* __restrict__ enc) {
    int b = blockIdx.x;
    int h = threadIdx.x & 127;
    int part = threadIdx.x >> 7;
    float sum = 0.f;
    int n0 = part * 500;
    for (int n = n0; n < n0 + 500; n++) sum += enc[(size_t)(b * Nn + n) * Hh + h];
    __shared__ float sp[256];
    sp[threadIdx.x] = sum;
    __syncthreads();
    if (part == 0) d_hmean[b * Hh + h] = (sp[h] + sp[128 + h]) * (1.0f / (float)Nn);
}

// ---------------- init: mask copy + first-step Wq1 projection ----------------
__global__ __launch_bounds__(256) void init_kernel(const float* __restrict__ mask0,
                                                   const float* __restrict__ dec_inp,
                                                   const float* __restrict__ Wq1) {
    int b = blockIdx.x, tid = threadIdx.x;
    __shared__ float sq0[256];
    sq0[tid] = (tid < 128) ? d_hmean[b * Hh + tid] : dec_inp[tid - 128];
    for (int n = tid; n < Nn; n += 256) d_mask[b * Nn + n] = mask0[b * Nn + n];
    __syncthreads();
    int m = tid >> 7, h = tid & 127;
    const float* W = Wq1 + (size_t)m * 256 * Hh;
    float acc = 0.f;
#pragma unroll 8
    for (int i = 0; i < 256; i++) acc = fmaf(sq0[i], W[(size_t)i * Hh + h], acc);
    d_qproj[(b * Mm + m) * Hh + h] = acc;
}

// ---------------- glimpse chunk: padded-1024 scan, 8 rows/warp ---------------------
// grid (Ss=16, Mm, Bb) = 512 blocks -> ONE wave at 4 blocks/SM. 8 warps x 8 rows.
// Rows n >= Nn get p forced to 0 (padding); their loads hit valid (padded) memory.
// Raw bf16 words kept live; converted twice (dot phase, accumulate phase) to cap regs.
__global__ __launch_bounds__(256, 4) void glimpse_chunk(int which) {
    const __nv_bfloat16* rT = (which == 0) ? d_r1 : (which == 1) ? d_r3 : d_r4;
    const __nv_bfloat16* vT = (which == 0) ? d_v1 : (which == 1) ? d_v3 : d_v4;

    int c = blockIdx.x, m = blockIdx.y, b = blockIdx.z;
    int tid = threadIdx.x, lane = tid & 31, w = tid >> 5;

    __shared__ float wZ[8];
    __shared__ __align__(16) float wacc[8 * 128];

    float4 q4 = *(const float4*)&d_qproj[((size_t)(b * Mm + m)) * Hh + lane * 4];
    const __nv_bfloat16* rBase = rT + (size_t)(m * Bb + b) * Nn * Hh;
    const __nv_bfloat16* vBase = vT + (size_t)(m * Bb + b) * Nn * Hh;
    const float* maskb = d_mask + b * Nn;

    int n0 = c * CN + w;

    // front-batched loads: 17 independent LDGs in flight per warp
    uint2 rw[8], vw[8];
    float mk[8];
#pragma unroll
    for (int i = 0; i < 8; i++) {
        int n = n0 + i * 8;
        rw[i] = *(const uint2*)&rBase[(size_t)n * Hh + lane * 4];
        vw[i] = *(const uint2*)&vBase[(size_t)n * Hh + lane * 4];
        mk[i] = maskb[n];
    }

    // phase 1: per-row dot products (convert on the fly; vw dies here)
    float dot[8];
#pragma unroll
    for (int i = 0; i < 8; i++) {
        float2 r01 = __bfloat1622float2(*(__nv_bfloat162*)&rw[i].x);
        float2 r23 = __bfloat1622float2(*(__nv_bfloat162*)&rw[i].y);
        float2 v01 = __bfloat1622float2(*(__nv_bfloat162*)&vw[i].x);
        float2 v23 = __bfloat1622float2(*(__nv_bfloat162*)&vw[i].y);
        float d = fast_tanh(q4.x + r01.x) * v01.x;
        d = fmaf(fast_tanh(q4.y + r01.y), v01.y, d);
        d = fmaf(fast_tanh(q4.z + r23.x), v23.x, d);
        d = fmaf(fast_tanh(q4.w + r23.y), v23.y, d);
        dot[i] = d;
    }
    // 8 interleaved butterfly reductions (independent chains hide shfl latency)
#pragma unroll
    for (int off = 16; off; off >>= 1) {
#pragma unroll
        for (int i = 0; i < 8; i++) dot[i] += __shfl_xor_sync(0xffffffffu, dot[i], off);
    }

    // phase 2: weights + weighted accumulation of r (reconvert rw)
    float Z = 0.f;
    float4 racc = make_float4(0.f, 0.f, 0.f, 0.f);
#pragma unroll
    for (int i = 0; i < 8; i++) {
        float p = __expf(fmaf(CCLIP, fast_tanh(dot[i]), -CCLIP) - NEGC * mk[i]);
        int n = n0 + i * 8;
        p = (n < Nn) ? p : 0.f;          // padding rows contribute nothing
        Z += p;
        float2 r01 = __bfloat1622float2(*(__nv_bfloat162*)&rw[i].x);
        float2 r23 = __bfloat1622float2(*(__nv_bfloat162*)&rw[i].y);
        racc.x = fmaf(p, r01.x, racc.x);
        racc.y = fmaf(p, r01.y, racc.y);
        racc.z = fmaf(p, r23.x, racc.z);
        racc.w = fmaf(p, r23.y, racc.w);
    }

    if (lane == 0) wZ[w] = Z;
    *(float4*)&wacc[w * 128 + lane * 4] = racc;
    __syncthreads();

    if (tid < 128) {
        float z = 0.f, g = 0.f;
#pragma unroll
        for (int j = 0; j < 8; j++) {
            z += wZ[j];
            g += wacc[j * 128 + tid];
        }
        int pidx = (b * Mm + m) * Ss + c;
        d_pacc[pidx * Hh + tid] = g;
        if (tid == 0) d_pZ[pidx] = z;
    }
}

// ---------------- combine: merge chunks + heads, project NEXT query --------------
// last==0: project with Wqnext[M,H,H] -> d_qproj. last==1: project with Wq2[H,H] -> d_qp2.
__global__ __launch_bounds__(256) void glimpse_combine(const float* __restrict__ Wmh,
                                                       const float* __restrict__ Wqnext,
                                                       int last,
                                                       const float* __restrict__ Wq2) {
    int b = blockIdx.x, tid = threadIdx.x;   // tid = m*128 + h
    __shared__ float sg[256];
    __shared__ float sp2[256];
    __shared__ __align__(16) float sqb[128];
    int base = (b * Mm + (tid >> 7)) * Ss;
    int h = tid & 127;
    float z = 0.f, g = 0.f;
#pragma unroll
    for (int c = 0; c < Ss; c++) {
        z += d_pZ[base + c];
        g += d_pacc[(base + c) * Hh + h];
    }
    sg[tid] = g / z;
    __syncthreads();
    // qb[h] = sum_j sg[j] * Wmh[j,h]
    {
        int part = tid >> 7;
        int j0 = part * 128;
        float o = 0.f;
#pragma unroll 8
        for (int j = j0; j < j0 + 128; j++) o = fmaf(sg[j], Wmh[(size_t)j * Hh + h], o);
        sp2[tid] = o;
        __syncthreads();
        if (part == 0) sqb[h] = sp2[h] + sp2[128 + h];
        __syncthreads();
    }
    if (!last) {
        int m = tid >> 7;
        const float* W = Wqnext + (size_t)m * Hh * Hh;
        float acc = 0.f;
#pragma unroll 8
        for (int i = 0; i < 128; i++) acc = fmaf(sqb[i], W[(size_t)i * Hh + h], acc);
        d_qproj[(b * Mm + m) * Hh + h] = acc;
    } else {
        int part = tid >> 7;
        int i0 = part * 64;
        float acc = 0.f;
#pragma unroll 8
        for (int i = i0; i < i0 + 64; i++) acc = fmaf(sqb[i], Wq2[(size_t)i * Hh + h], acc);
        sp2[tid] = acc;
        __syncthreads();
        if (part == 0) d_qp2[b * Hh + h] = sp2[h] + sp2[128 + h];
    }
}

// ---------------- pointer logits: padded-1024 scan over r2 (fp32), 8 rows/warp -----
// grid (SsL=16, Bb) = 256 blocks. Writes guarded to n < Nn.
__global__ __launch_bounds__(256, 3) void logits_chunk(const float* __restrict__ Vec2) {
    int c = blockIdx.x, b = blockIdx.y;
    int tid = threadIdx.x, lane = tid & 31, w = tid >> 5;

    float4 q4 = *(const float4*)&d_qp2[b * Hh + lane * 4];
    float4 v2 = *(const float4*)&Vec2[lane * 4];
    const float* rBase = d_r2 + (size_t)b * Nn * Hh;
    const float* maskb = d_mask + b * Nn;

    int n0 = c * CN + w;
    float4 r[8];
    float mk[8];
#pragma unroll
    for (int i = 0; i < 8; i++) {
        int n = n0 + i * 8;
        r[i] = *(const float4*)&rBase[(size_t)n * Hh + lane * 4];
        mk[i] = maskb[n];
    }
    float dot[8];
#pragma unroll
    for (int i = 0; i < 8; i++) {
        float d = fast_tanh(q4.x + r[i].x) * v2.x;
        d = fmaf(fast_tanh(q4.y + r[i].y), v2.y, d);
        d = fmaf(fast_tanh(q4.z + r[i].z), v2.z, d);
        d = fmaf(fast_tanh(q4.w + r[i].w), v2.w, d);
        dot[i] = d;
    }
#pragma unroll
    for (int off = 16; off; off >>= 1) {
#pragma unroll
        for (int i = 0; i < 8; i++) dot[i] += __shfl_xor_sync(0xffffffffu, dot[i], off);
    }
    if (lane == 0) {
#pragma unroll
        for (int i = 0; i < 8; i++) {
            int n = n0 + i * 8;
            if (n < Nn)
                d_u[b * Nn + n] = CCLIP * fast_tanh(dot[i]) - NEGC * mk[i];
        }
    }
}

// ---------------- finalize: log_softmax, argmax, output, state, next projection ----
__global__ __launch_bounds__(1024) void pointer_finalize(const float* __restrict__ enc,
                                                         const float* __restrict__ Wq1,
                                                         float* __restrict__ out, int t) {
    int b = blockIdx.x, tid = threadIdx.x;
    __shared__ float rv[1024];
    __shared__ int ri[1024];
    __shared__ float sred[1024];
    __shared__ float sq0[256];

    float u = (tid < Nn) ? d_u[b * Nn + tid] : -1e30f;

    // argmax (first index wins on ties, matching jnp.argmax)
    rv[tid] = u; ri[tid] = (tid < Nn) ? tid : 0;
    __syncthreads();
#pragma unroll
    for (int s = 512; s; s >>= 1) {
        if (tid < s) {
            float v2 = rv[tid + s]; int i2 = ri[tid + s];
            if (v2 > rv[tid] || (v2 == rv[tid] && i2 < ri[tid])) { rv[tid] = v2; ri[tid] = i2; }
        }
        __syncthreads();
    }
    int sel = ri[0];

    // fixed-shift lse: u <= 10 always
    sred[tid] = (tid < Nn) ? __expf(u - CCLIP) : 0.f;
    __syncthreads();
#pragma unroll
    for (int s = 512; s; s >>= 1) {
        if (tid < s) sred[tid] += sred[tid + s];
        __syncthreads();
    }
    float lse = CCLIP + __logf(sred[0]);

    if (tid < Nn)
        out[((size_t)t * Bb + b) * Nn + tid] = u - lse;
    if (tid == 0) {
        out[(size_t)Tt * Bb * Nn + t * Bb + b] = (float)sel;
        d_mask[b * Nn + sel] = 1.0f;
    }

    // q0 = [h_mean, enc[b, sel]]; project with Wq1 for next step's glimpse 1
    if (tid < 256)
        sq0[tid] = (tid < 128) ? d_hmean[b * Hh + tid]
                               : enc[((size_t)b * Nn + sel) * Hh + (tid - 128)];
    __syncthreads();
    {
        int part = tid >> 8;          // 4 parts
        int mh = tid & 255;
        int m = mh >> 7, h = mh & 127;
        const float* W = Wq1 + (size_t)m * 256 * Hh;
        int i0 = part * 64;
        float acc = 0.f;
#pragma unroll 8
        for (int i = i0; i < i0 + 64; i++) acc = fmaf(sq0[i], W[(size_t)i * Hh + h], acc);
        sred[tid] = acc;
        __syncthreads();
        if (tid < 256) {
            float a = sred[tid] + sred[tid + 256] + sred[tid + 512] + sred[tid + 768];
            d_qproj[(b * Mm + m) * Hh + h] = a;
        }
    }
}

// ---------------- host launcher ----------------
extern "C" void kernel_launch(void* const* d_in, const int* in_sizes, int n_in,
                              void* d_out, int out_size) {
    const float* enc    = (const float*)d_in[0];
    const float* mask0  = (const float*)d_in[1];
    const float* Wq1    = (const float*)d_in[2];
    const float* Wref1  = (const float*)d_in[3];
    const float* Vec1   = (const float*)d_in[4];
    const float* Wq3    = (const float*)d_in[5];
    const float* Wref3  = (const float*)d_in[6];
    const float* Vec3   = (const float*)d_in[7];
    const float* Wq4    = (const float*)d_in[8];
    const float* Wref4  = (const float*)d_in[9];
    const float* Vec4   = (const float*)d_in[10];
    const float* Wmh    = (const float*)d_in[11];
    const float* Wq2    = (const float*)d_in[12];
    const float* Wref2  = (const float*)d_in[13];
    const float* Vec2   = (const float*)d_in[14];
    const float* dec_inp = (const float*)d_in[15];
    float* out = (float*)d_out;

    GemmW gw{Wref1, Vec1, Wref3, Vec3, Wref4, Vec4, Wref2};
    gemm_kernel<<<dim3(125, 13), 256>>>(enc, gw);
    hmean_kernel<<<Bb, 256>>>(enc);
    init_kernel<<<Bb, 256>>>(mask0, dec_inp, Wq1);

    for (int t = 0; t < Tt; t++) {
        glimpse_chunk<<<dim3(Ss, Mm, Bb), 256>>>(0);
        glimpse_combine<<<Bb, 256>>>(Wmh, Wq3, 0, Wq2);
        glimpse_chunk<<<dim3(Ss, Mm, Bb), 256>>>(1);
        glimpse_combine<<<Bb, 256>>>(Wmh, Wq4, 0, Wq2);
        glimpse_chunk<<<dim3(Ss, Mm, Bb), 256>>>(2);
        glimpse_combine<<<Bb, 256>>>(Wmh, Wq4, 1, Wq2);
        logits_chunk<<<dim3(SsL, Bb), 256>>>(Vec2);
        pointer_finalize<<<Bb, 1024>>>(enc, Wq1, out, t);
    }
    (void)in_sizes; (void)n_in; (void)out_size;
}

// round 15
// speedup vs baseline: 1.2266x; 1.0975x over previous
#include <cuda_runtime.h>
#include <cuda_bf16.h>
#include <math.h>

#define Bb 16
#define Nn 1000
#define NP 1024       // padded scan length (rows >= Nn forced to weight 0)
#define Hh 128
#define Mm 2
#define Tt 16
#define Ss 16         // chunks per (b,m): CN rows each (over padded NP)
#define CN 64         // NP / Ss; 8 warps x 8 rows
#define NEGC 1e8f
#define CCLIP 10.0f

// ---------------- scratch (static device globals; no allocation) ----------------
// r/v arrays padded by 32 rows so padded reads stay in-bounds (earlier slabs
// overrun into the next slab: valid memory, contribution masked to 0).
#define BNH (Bb*Nn*Hh)
#define PAD (32*Hh)
__device__ __align__(16) __nv_bfloat16 d_r1[Mm*BNH + PAD];
__device__ __align__(16) __nv_bfloat16 d_v1[Mm*BNH + PAD];
__device__ __align__(16) __nv_bfloat16 d_r3[Mm*BNH + PAD];
__device__ __align__(16) __nv_bfloat16 d_v3[Mm*BNH + PAD];
__device__ __align__(16) __nv_bfloat16 d_r4[Mm*BNH + PAD];
__device__ __align__(16) __nv_bfloat16 d_v4[Mm*BNH + PAD];
__device__ __align__(16) float d_r2[BNH + PAD];    // pointer path stays fp32
__device__ __align__(16) float d_hmean[Bb*Hh];
__device__ __align__(16) float d_qproj[Bb*Mm*Hh];  // projected glimpse query per head
__device__ __align__(16) float d_qp2[Bb*Hh];       // projected pointer query
__device__ __align__(16) float d_mask[Bb*Nn + 64];
__device__ __align__(16) float d_pZ[Bb*Mm*Ss];
__device__ __align__(16) float d_pacc[Bb*Mm*Ss*Hh];

__device__ __forceinline__ float fast_tanh(float x) {
    float y;
    asm("tanh.approx.f32 %0, %1;" : "=f"(y) : "f"(x));
    return y;
}

// ---------------- precompute GEMM: 13 slabs of [16000x128] @ [128x128] (SIMT) ------
struct GemmW {
    const float* Wref1; const float* Vec1;
    const float* Wref3; const float* Vec3;
    const float* Wref4; const float* Vec4;
    const float* Wref2;
};

__global__ __launch_bounds__(256) void gemm_kernel(const float* __restrict__ A, GemmW gw) {
    __shared__ float As[8][132];
    __shared__ float Bs[8][132];

    int s = blockIdx.y;
    int m = s & 1;
    const float* W;
    __nv_bfloat16* Db = nullptr;
    float* Df = nullptr;
    switch (s >> 1) {
        case 0: W = gw.Wref1; Db = d_r1; break;
        case 1: W = gw.Vec1;  Db = d_v1; break;
        case 2: W = gw.Wref3; Db = d_r3; break;
        case 3: W = gw.Vec3;  Db = d_v3; break;
        case 4: W = gw.Wref4; Db = d_r4; break;
        case 5: W = gw.Vec4;  Db = d_v4; break;
        default: W = gw.Wref2; Df = d_r2; break;   // s==12 -> m==0
    }
    W += (size_t)m * Hh * Hh;
    if (Db) Db += (size_t)m * BNH;

    int tid = threadIdx.x;
    int tx = tid & 15, ty = tid >> 4;
    int rowBase = blockIdx.x * 128;

    int arow = tid >> 1, akq = (tid & 1) * 4;
    int brow = tid >> 5, bcol = (tid & 31) * 4;

    float acc[8][8];
#pragma unroll
    for (int i = 0; i < 8; i++)
#pragma unroll
        for (int j = 0; j < 8; j++) acc[i][j] = 0.f;

    for (int k0 = 0; k0 < 128; k0 += 8) {
        float4 av = *(const float4*)&A[(size_t)(rowBase + arow) * 128 + k0 + akq];
        As[akq + 0][arow] = av.x;
        As[akq + 1][arow] = av.y;
        As[akq + 2][arow] = av.z;
        As[akq + 3][arow] = av.w;
        float4 bv = *(const float4*)&W[(size_t)(k0 + brow) * 128 + bcol];
        *(float4*)&Bs[brow][bcol] = bv;
        __syncthreads();
#pragma unroll
        for (int kk = 0; kk < 8; kk++) {
            float4 a0 = *(float4*)&As[kk][ty * 8];
            float4 a1 = *(float4*)&As[kk][ty * 8 + 4];
            float4 b0 = *(float4*)&Bs[kk][tx * 4];
            float4 b1 = *(float4*)&Bs[kk][64 + tx * 4];
            float a[8] = {a0.x, a0.y, a0.z, a0.w, a1.x, a1.y, a1.z, a1.w};
            float b[8] = {b0.x, b0.y, b0.z, b0.w, b1.x, b1.y, b1.z, b1.w};
#pragma unroll
            for (int i = 0; i < 8; i++)
#pragma unroll
                for (int j = 0; j < 8; j++) acc[i][j] = fmaf(a[i], b[j], acc[i][j]);
        }
        __syncthreads();
    }

    int r0 = rowBase + ty * 8;
    if (Db) {
#pragma unroll
        for (int i = 0; i < 8; i++) {
            __nv_bfloat162 p01 = __floats2bfloat162_rn(acc[i][0], acc[i][1]);
            __nv_bfloat162 p23 = __floats2bfloat162_rn(acc[i][2], acc[i][3]);
            __nv_bfloat162 p45 = __floats2bfloat162_rn(acc[i][4], acc[i][5]);
            __nv_bfloat162 p67 = __floats2bfloat162_rn(acc[i][6], acc[i][7]);
            uint2 lo, hi;
            lo.x = *(unsigned int*)&p01; lo.y = *(unsigned int*)&p23;
            hi.x = *(unsigned int*)&p45; hi.y = *(unsigned int*)&p67;
            *(uint2*)&Db[(size_t)(r0 + i) * Hh + tx * 4] = lo;
            *(uint2*)&Db[(size_t)(r0 + i) * Hh + 64 + tx * 4] = hi;
        }
    } else {
#pragma unroll
        for (int i = 0; i < 8; i++) {
            float4 o0 = make_float4(acc[i][0], acc[i][1], acc[i][2], acc[i][3]);
            float4 o1 = make_float4(acc[i][4], acc[i][5], acc[i][6], acc[i][7]);
            *(float4*)&Df[(size_t)(r0 + i) * Hh + tx * 4] = o0;
            *(float4*)&Df[(size_t)(r0 + i) * Hh + 64 + tx * 4] = o1;
        }
    }
}

// ---------------- h_mean ----------------
__global__ __launch_bounds__(256) void hmean_kernel(const float* __restrict__ enc) {
    int b = blockIdx.x;
    int h = threadIdx.x & 127;
    int part = threadIdx.x >> 7;
    float sum = 0.f;
    int n0 = part * 500;
    for (int n = n0; n < n0 + 500; n++) sum += enc[(size_t)(b * Nn + n) * Hh + h];
    __shared__ float sp[256];
    sp[threadIdx.x] = sum;
    __syncthreads();
    if (part == 0) d_hmean[b * Hh + h] = (sp[h] + sp[128 + h]) * (1.0f / (float)Nn);
}

// ---------------- init: mask copy + first-step Wq1 projection ----------------
__global__ __launch_bounds__(256) void init_kernel(const float* __restrict__ mask0,
                                                   const float* __restrict__ dec_inp,
                                                   const float* __restrict__ Wq1) {
    int b = blockIdx.x, tid = threadIdx.x;
    __shared__ float sq0[256];
    sq0[tid] = (tid < 128) ? d_hmean[b * Hh + tid] : dec_inp[tid - 128];
    for (int n = tid; n < Nn; n += 256) d_mask[b * Nn + n] = mask0[b * Nn + n];
    __syncthreads();
    int m = tid >> 7, h = tid & 127;
    const float* W = Wq1 + (size_t)m * 256 * Hh;
    float acc = 0.f;
#pragma unroll 8
    for (int i = 0; i < 256; i++) acc = fmaf(sq0[i], W[(size_t)i * Hh + h], acc);
    d_qproj[(b * Mm + m) * Hh + h] = acc;
}

// ---------------- glimpse chunk: padded-1024 scan, 8 rows/warp (unchanged R14) -----
__global__ __launch_bounds__(256, 4) void glimpse_chunk(int which) {
    const __nv_bfloat16* rT = (which == 0) ? d_r1 : (which == 1) ? d_r3 : d_r4;
    const __nv_bfloat16* vT = (which == 0) ? d_v1 : (which == 1) ? d_v3 : d_v4;

    int c = blockIdx.x, m = blockIdx.y, b = blockIdx.z;
    int tid = threadIdx.x, lane = tid & 31, w = tid >> 5;

    __shared__ float wZ[8];
    __shared__ __align__(16) float wacc[8 * 128];

    float4 q4 = *(const float4*)&d_qproj[((size_t)(b * Mm + m)) * Hh + lane * 4];
    const __nv_bfloat16* rBase = rT + (size_t)(m * Bb + b) * Nn * Hh;
    const __nv_bfloat16* vBase = vT + (size_t)(m * Bb + b) * Nn * Hh;
    const float* maskb = d_mask + b * Nn;

    int n0 = c * CN + w;

    uint2 rw[8], vw[8];
    float mk[8];
#pragma unroll
    for (int i = 0; i < 8; i++) {
        int n = n0 + i * 8;
        rw[i] = *(const uint2*)&rBase[(size_t)n * Hh + lane * 4];
        vw[i] = *(const uint2*)&vBase[(size_t)n * Hh + lane * 4];
        mk[i] = maskb[n];
    }

    float dot[8];
#pragma unroll
    for (int i = 0; i < 8; i++) {
        float2 r01 = __bfloat1622float2(*(__nv_bfloat162*)&rw[i].x);
        float2 r23 = __bfloat1622float2(*(__nv_bfloat162*)&rw[i].y);
        float2 v01 = __bfloat1622float2(*(__nv_bfloat162*)&vw[i].x);
        float2 v23 = __bfloat1622float2(*(__nv_bfloat162*)&vw[i].y);
        float d = fast_tanh(q4.x + r01.x) * v01.x;
        d = fmaf(fast_tanh(q4.y + r01.y), v01.y, d);
        d = fmaf(fast_tanh(q4.z + r23.x), v23.x, d);
        d = fmaf(fast_tanh(q4.w + r23.y), v23.y, d);
        dot[i] = d;
    }
#pragma unroll
    for (int off = 16; off; off >>= 1) {
#pragma unroll
        for (int i = 0; i < 8; i++) dot[i] += __shfl_xor_sync(0xffffffffu, dot[i], off);
    }

    float Z = 0.f;
    float4 racc = make_float4(0.f, 0.f, 0.f, 0.f);
#pragma unroll
    for (int i = 0; i < 8; i++) {
        float p = __expf(fmaf(CCLIP, fast_tanh(dot[i]), -CCLIP) - NEGC * mk[i]);
        int n = n0 + i * 8;
        p = (n < Nn) ? p : 0.f;
        Z += p;
        float2 r01 = __bfloat1622float2(*(__nv_bfloat162*)&rw[i].x);
        float2 r23 = __bfloat1622float2(*(__nv_bfloat162*)&rw[i].y);
        racc.x = fmaf(p, r01.x, racc.x);
        racc.y = fmaf(p, r01.y, racc.y);
        racc.z = fmaf(p, r23.x, racc.z);
        racc.w = fmaf(p, r23.y, racc.w);
    }

    if (lane == 0) wZ[w] = Z;
    *(float4*)&wacc[w * 128 + lane * 4] = racc;
    __syncthreads();

    if (tid < 128) {
        float z = 0.f, g = 0.f;
#pragma unroll
        for (int j = 0; j < 8; j++) {
            z += wZ[j];
            g += wacc[j * 128 + tid];
        }
        int pidx = (b * Mm + m) * Ss + c;
        d_pacc[pidx * Hh + tid] = g;
        if (tid == 0) d_pZ[pidx] = z;
    }
}

// ---------------- combine: 512 threads, 4-way-split matvecs ------------------------
// last==0: project with Wqnext[M,H,H] -> d_qproj. last==1: project with Wq2 -> d_qp2.
__global__ __launch_bounds__(512) void glimpse_combine(const float* __restrict__ Wmh,
                                                       const float* __restrict__ Wqnext,
                                                       int last,
                                                       const float* __restrict__ Wq2) {
    int b = blockIdx.x, tid = threadIdx.x;
    int q2 = tid >> 8;          // 0/1
    int mh = tid & 255;
    int m = mh >> 7, h = mh & 127;

    __shared__ float spz[512], spg[512];
    __shared__ float sg[256];
    __shared__ float sp[512];
    __shared__ __align__(16) float sqb[128];

    // chunk sums: 16 chunks split 8/8 across q2
    {
        int base = (b * Mm + m) * Ss;
        float z = 0.f, g = 0.f;
#pragma unroll
        for (int c = q2 * 8; c < q2 * 8 + 8; c++) {
            z += d_pZ[base + c];
            g += d_pacc[(base + c) * Hh + h];
        }
        spz[tid] = z; spg[tid] = g;
        __syncthreads();
        if (tid < 256) {
            float zz = spz[tid] + spz[tid + 256];
            float gg = spg[tid] + spg[tid + 256];
            sg[tid] = gg / zz;
        }
        __syncthreads();
    }
    // qb[h] = sum_{j<256} sg[j]*Wmh[j,h]; 4-way split
    {
        int p = tid >> 7, hh = tid & 127;
        int j0 = p * 64;
        float o = 0.f;
#pragma unroll 8
        for (int j = j0; j < j0 + 64; j++) o = fmaf(sg[j], Wmh[(size_t)j * Hh + hh], o);
        sp[tid] = o;
        __syncthreads();
        if (tid < 128) sqb[tid] = sp[tid] + sp[tid + 128] + sp[tid + 256] + sp[tid + 384];
        __syncthreads();
    }
    if (!last) {
        // q[m][h] = sum_i sqb[i]*Wqnext[m,i,h]; i split 64/64 across q2
        const float* W = Wqnext + (size_t)m * Hh * Hh;
        int i0 = q2 * 64;
        float acc = 0.f;
#pragma unroll 8
        for (int i = i0; i < i0 + 64; i++) acc = fmaf(sqb[i], W[(size_t)i * Hh + h], acc);
        sp[tid] = acc;
        __syncthreads();
        if (tid < 256) d_qproj[(b * Mm + m) * Hh + h] = sp[tid] + sp[tid + 256];
    } else {
        // qp2[h] = sum_i sqb[i]*Wq2[i,h]; 4-way split
        int p = tid >> 7, hh = tid & 127;
        int i0 = p * 32;
        float acc = 0.f;
#pragma unroll 8
        for (int i = i0; i < i0 + 32; i++) acc = fmaf(sqb[i], Wq2[(size_t)i * Hh + hh], acc);
        sp[tid] = acc;
        __syncthreads();
        if (tid < 128) d_qp2[b * Hh + tid] = sp[tid] + sp[tid + 128] + sp[tid + 256] + sp[tid + 384];
    }
}

// ---------------- fused pointer: logits + log_softmax + argmax + state -------------
// grid Bb, 1024 threads (32 warps). Each warp computes rows n = w + 32*s, s<32,
// 4-row batches for MLP; then block-wide argmax/lse/output/state/projection.
__global__ __launch_bounds__(1024) void pointer_kernel(const float* __restrict__ enc,
                                                       const float* __restrict__ Wq1,
                                                       const float* __restrict__ Vec2,
                                                       float* __restrict__ out, int t) {
    int b = blockIdx.x, tid = threadIdx.x, lane = tid & 31, w = tid >> 5;
    __shared__ float su[Nn];
    __shared__ float rv[1024];
    __shared__ int ri[1024];
    __shared__ float sred[1024];
    __shared__ float sq0[256];

    // ---- logits ----
    {
        float4 q4 = *(const float4*)&d_qp2[b * Hh + lane * 4];
        float4 v2 = *(const float4*)&Vec2[lane * 4];
        const float* rBase = d_r2 + (size_t)b * Nn * Hh;
        const float* maskb = d_mask + b * Nn;
#pragma unroll
        for (int j = 0; j < 8; j++) {
            float4 r[4]; float mk[4];
#pragma unroll
            for (int k = 0; k < 4; k++) {
                int n = w + (j * 4 + k) * 32;
                if (n < Nn) {
                    r[k] = *(const float4*)&rBase[(size_t)n * Hh + lane * 4];
                    mk[k] = maskb[n];
                } else {
                    r[k] = make_float4(0.f, 0.f, 0.f, 0.f);
                    mk[k] = 0.f;
                }
            }
            float dot[4];
#pragma unroll
            for (int k = 0; k < 4; k++) {
                float d = fast_tanh(q4.x + r[k].x) * v2.x;
                d = fmaf(fast_tanh(q4.y + r[k].y), v2.y, d);
                d = fmaf(fast_tanh(q4.z + r[k].z), v2.z, d);
                d = fmaf(fast_tanh(q4.w + r[k].w), v2.w, d);
                dot[k] = d;
            }
#pragma unroll
            for (int off = 16; off; off >>= 1) {
#pragma unroll
                for (int k = 0; k < 4; k++) dot[k] += __shfl_xor_sync(0xffffffffu, dot[k], off);
            }
            if (lane == 0) {
#pragma unroll
                for (int k = 0; k < 4; k++) {
                    int n = w + (j * 4 + k) * 32;
                    if (n < Nn)
                        su[n] = CCLIP * fast_tanh(dot[k]) - NEGC * maskb[n];
                }
            }
        }
    }
    __syncthreads();

    float u = (tid < Nn) ? su[tid] : -1e30f;

    // argmax (first index wins on ties, matching jnp.argmax)
    rv[tid] = u; ri[tid] = (tid < Nn) ? tid : 0;
    __syncthreads();
#pragma unroll
    for (int s = 512; s; s >>= 1) {
        if (tid < s) {
            float v2r = rv[tid + s]; int i2 = ri[tid + s];
            if (v2r > rv[tid] || (v2r == rv[tid] && i2 < ri[tid])) { rv[tid] = v2r; ri[tid] = i2; }
        }
        __syncthreads();
    }
    int sel = ri[0];

    // fixed-shift lse: u <= 10 always
    sred[tid] = (tid < Nn) ? __expf(u - CCLIP) : 0.f;
    __syncthreads();
#pragma unroll
    for (int s = 512; s; s >>= 1) {
        if (tid < s) sred[tid] += sred[tid + s];
        __syncthreads();
    }
    float lse = CCLIP + __logf(sred[0]);

    if (tid < Nn)
        out[((size_t)t * Bb + b) * Nn + tid] = u - lse;
    if (tid == 0) {
        out[(size_t)Tt * Bb * Nn + t * Bb + b] = (float)sel;
        d_mask[b * Nn + sel] = 1.0f;
    }

    // q0 = [h_mean, enc[b, sel]]; project with Wq1 for next step's glimpse 1
    if (tid < 256)
        sq0[tid] = (tid < 128) ? d_hmean[b * Hh + tid]
                               : enc[((size_t)b * Nn + sel) * Hh + (tid - 128)];
    __syncthreads();
    {
        int part = tid >> 8;          // 4 parts
        int mh = tid & 255;
        int m = mh >> 7, h = mh & 127;
        const float* W = Wq1 + (size_t)m * 256 * Hh;
        int i0 = part * 64;
        float acc = 0.f;
#pragma unroll 8
        for (int i = i0; i < i0 + 64; i++) acc = fmaf(sq0[i], W[(size_t)i * Hh + h], acc);
        sred[tid] = acc;
        __syncthreads();
        if (tid < 256) {
            float a = sred[tid] + sred[tid + 256] + sred[tid + 512] + sred[tid + 768];
            d_qproj[(b * Mm + m) * Hh + h] = a;
        }
    }
}

// ---------------- host launcher ----------------
extern "C" void kernel_launch(void* const* d_in, const int* in_sizes, int n_in,
                              void* d_out, int out_size) {
    const float* enc    = (const float*)d_in[0];
    const float* mask0  = (const float*)d_in[1];
    const float* Wq1    = (const float*)d_in[2];
    const float* Wref1  = (const float*)d_in[3];
    const float* Vec1   = (const float*)d_in[4];
    const float* Wq3    = (const float*)d_in[5];
    const float* Wref3  = (const float*)d_in[6];
    const float* Vec3   = (const float*)d_in[7];
    const float* Wq4    = (const float*)d_in[8];
    const float* Wref4  = (const float*)d_in[9];
    const float* Vec4   = (const float*)d_in[10];
    const float* Wmh    = (const float*)d_in[11];
    const float* Wq2    = (const float*)d_in[12];
    const float* Wref2  = (const float*)d_in[13];
    const float* Vec2   = (const float*)d_in[14];
    const float* dec_inp = (const float*)d_in[15];
    float* out = (float*)d_out;

    GemmW gw{Wref1, Vec1, Wref3, Vec3, Wref4, Vec4, Wref2};
    gemm_kernel<<<dim3(125, 13), 256>>>(enc, gw);
    hmean_kernel<<<Bb, 256>>>(enc);
    init_kernel<<<Bb, 256>>>(mask0, dec_inp, Wq1);

    for (int t = 0; t < Tt; t++) {
        glimpse_chunk<<<dim3(Ss, Mm, Bb), 256>>>(0);
        glimpse_combine<<<Bb, 512>>>(Wmh, Wq3, 0, Wq2);
        glimpse_chunk<<<dim3(Ss, Mm, Bb), 256>>>(1);
        glimpse_combine<<<Bb, 512>>>(Wmh, Wq4, 0, Wq2);
        glimpse_chunk<<<dim3(Ss, Mm, Bb), 256>>>(2);
        glimpse_combine<<<Bb, 512>>>(Wmh, Wq4, 1, Wq2);
        pointer_kernel<<<Bb, 1024>>>(enc, Wq1, Vec2, out, t);
    }
    (void)in_sizes; (void)n_in; (void)out_size;
}